// round 6
// baseline (speedup 1.0000x reference)
#include <cuda_runtime.h>
#include <cstdint>

// StreamingSTFT collapses analytically:
//   irfft(rfft(x)) == x  =>  frame = in_buf * aw * sw
//   sw nonzero only on [96,160)  =>  overlap-add reduces to
//   out[i][j] = chunk[i-3][j] * W[j]   (i >= 3), else 0
//   W[j] = aw[j+128]*sw[j+128] (j<32) ; aw[j+64]*sw[j+64] (j>=32)
//
// R5 (= R4 resubmit after infra failure): 256-bit (.v8.b32) global
// loads/stores — halves warp-level memory instructions at identical byte
// traffic. Balanced 148*8 grid; launch_bounds(256,8) caps regs for full
// 2048-thread/SM residency.

static constexpr int HOP = 64;
static constexpr long long NUM_FRAMES = 131072;
static constexpr int N_VEC8 = (int)(NUM_FRAMES * HOP / 8);   // 1,048,576 float8s
static constexpr int DELAY_VEC8 = (3 * HOP) / 8;             // 24 float8s = 3 rows

static constexpr int NUM_SMS = 148;
static constexpr int BLOCKS  = NUM_SMS * 8;                  // 1184
static constexpr int THREADS = 256;
static constexpr int STRIDE  = BLOCKS * THREADS;             // 303104, %8 == 0
static constexpr int ITERS   = 4;                            // ceil(N_VEC8/STRIDE)

__device__ __forceinline__ void ldg256(const float* p, float r[8]) {
    asm volatile("ld.global.L2::evict_last.v8.b32 "
                 "{%0,%1,%2,%3,%4,%5,%6,%7}, [%8];"
                 : "=f"(r[0]), "=f"(r[1]), "=f"(r[2]), "=f"(r[3]),
                   "=f"(r[4]), "=f"(r[5]), "=f"(r[6]), "=f"(r[7])
                 : "l"(p));
}

__device__ __forceinline__ void stg256(float* p, const float r[8]) {
    asm volatile("st.global.L2::evict_last.v8.b32 "
                 "[%0], {%1,%2,%3,%4,%5,%6,%7,%8};"
                 :: "l"(p),
                    "f"(r[0]), "f"(r[1]), "f"(r[2]), "f"(r[3]),
                    "f"(r[4]), "f"(r[5]), "f"(r[6]), "f"(r[7])
                 : "memory");
}

__global__ void __launch_bounds__(THREADS, 8)
stft_delay_scale_kernel(const float* __restrict__ chunk,
                        const float* __restrict__ aw,
                        const float* __restrict__ sw,
                        float* __restrict__ out)
{
    const int i0 = blockIdx.x * THREADS + threadIdx.x;

    // Column group of this lane: 8 consecutive floats starting at j0.
    // j0 is a multiple of 8, so all 8 lie on the same window branch, and
    // STRIDE % 8 == 0 keeps it loop-invariant.
    const int j0   = (i0 & 7) << 3;                    // 0,8,...,56
    const int base = j0 + (j0 < 32 ? 128 : 64);

    float w[8];
#pragma unroll
    for (int t = 0; t < 8; t++) w[t] = aw[base + t] * sw[base + t];

#pragma unroll
    for (int k = 0; k < ITERS; k++) {
        const int i = i0 + k * STRIDE;
        if (i < N_VEC8) {
            float r[8];
            if (i >= DELAY_VEC8) {
                ldg256(chunk + (long long)(i - DELAY_VEC8) * 8, r);
#pragma unroll
                for (int t = 0; t < 8; t++) r[t] *= w[t];
            } else {
#pragma unroll
                for (int t = 0; t < 8; t++) r[t] = 0.f;
            }
            stg256(out + (long long)i * 8, r);
        }
    }
}

extern "C" void kernel_launch(void* const* d_in, const int* in_sizes, int n_in,
                              void* d_out, int out_size)
{
    const float* chunk = reinterpret_cast<const float*>(d_in[0]);
    const float* aw    = reinterpret_cast<const float*>(d_in[1]);
    const float* sw    = reinterpret_cast<const float*>(d_in[2]);
    float*       out   = reinterpret_cast<float*>(d_out);

    stft_delay_scale_kernel<<<BLOCKS, THREADS>>>(chunk, aw, sw, out);
}

// round 7
// speedup vs baseline: 1.1395x; 1.1395x over previous
#include <cuda_runtime.h>
#include <cstdint>

// StreamingSTFT collapses analytically:
//   irfft(rfft(x)) == x  =>  frame = in_buf * aw * sw
//   sw nonzero only on [96,160)  =>  overlap-add reduces to
//   out[i][j] = chunk[i-3][j] * W[j]   (i >= 3), else 0
//   W[j] = aw[j+128]*sw[j+128] (j<32) ; aw[j+64]*sw[j+64] (j>=32)
//
// R6: best-known shape (R1: plain __ldg float4, 8 front-batched loads,
// window hoisted) + perfectly balanced grid: 148*7 = 1036 blocks * 256
// threads = exactly 7 blocks/SM, single wave, no 6-vs-7 tail. No cache
// policies, no 256-bit ops (both measured as losses in R3/R5).

static constexpr int HOP = 64;
static constexpr long long NUM_FRAMES = 131072;
static constexpr long long N_VEC4 = NUM_FRAMES * HOP / 4;  // 2,097,152
static constexpr int DELAY_VEC4 = (3 * HOP) / 4;           // 48 float4s

static constexpr int NUM_SMS = 148;
static constexpr int BLOCKS  = NUM_SMS * 7;                // 1036
static constexpr int THREADS = 256;
static constexpr int STRIDE  = BLOCKS * THREADS;           // 265216, %16 == 0
static constexpr int ITERS   = 8;                          // 7 full + 1 partial

__global__ void __launch_bounds__(THREADS)
stft_delay_scale_kernel(const float4* __restrict__ chunk4,
                        const float*  __restrict__ aw,
                        const float*  __restrict__ sw,
                        float4* __restrict__ out4)
{
    const int i0 = blockIdx.x * THREADS + threadIdx.x;

    // Column of this lane within the 64-wide row; invariant across the
    // strided loop because STRIDE % 16 == 0.
    const int j0   = (i0 & 15) << 2;
    const int base = j0 + (j0 < 32 ? 128 : 64);            // float4-aligned

    const float4 a = *reinterpret_cast<const float4*>(aw + base);
    const float4 s = *reinterpret_cast<const float4*>(sw + base);
    const float4 w = make_float4(a.x * s.x, a.y * s.y, a.z * s.z, a.w * s.w);

    // Front-batch all independent loads (MLP = 8; last iter guarded).
    float4 v[ITERS];
#pragma unroll
    for (int k = 0; k < ITERS; k++) {
        const long long i = (long long)i0 + (long long)k * STRIDE;
        const bool in_range = (k < ITERS - 1) || (i < N_VEC4);
        if (in_range && i >= DELAY_VEC4) {
            v[k] = __ldg(chunk4 + (i - DELAY_VEC4));
        } else {
            v[k] = make_float4(0.f, 0.f, 0.f, 0.f);
        }
    }

#pragma unroll
    for (int k = 0; k < ITERS; k++) {
        const long long i = (long long)i0 + (long long)k * STRIDE;
        if (k < ITERS - 1 || i < N_VEC4) {
            float4 o;
            o.x = v[k].x * w.x;
            o.y = v[k].y * w.y;
            o.z = v[k].z * w.z;
            o.w = v[k].w * w.w;
            out4[i] = o;
        }
    }
}

extern "C" void kernel_launch(void* const* d_in, const int* in_sizes, int n_in,
                              void* d_out, int out_size)
{
    const float4* chunk4 = reinterpret_cast<const float4*>(d_in[0]);
    const float*  aw     = reinterpret_cast<const float*>(d_in[1]);
    const float*  sw     = reinterpret_cast<const float*>(d_in[2]);
    float4*       out4   = reinterpret_cast<float4*>(d_out);

    stft_delay_scale_kernel<<<BLOCKS, THREADS>>>(chunk4, aw, sw, out4);
}

// round 8
// speedup vs baseline: 1.1707x; 1.0274x over previous
#include <cuda_runtime.h>
#include <cstdint>

// StreamingSTFT collapses analytically:
//   irfft(rfft(x)) == x  =>  frame = in_buf * aw * sw
//   sw nonzero only on [96,160)  =>  overlap-add reduces to
//   out[i][j] = chunk[i-3][j] * W[j]   (i >= 3), else 0
//   W[j] = aw[j+128]*sw[j+128] (j<32) ; aw[j+64]*sw[j+64] (j>=32)
//
// R7: max-occupancy variant of the winning shape — 148*8 = 1184 blocks
// (64 warps/SM, single balanced wave), plain __ldg float4 with 7
// front-batched loads, window hoisted. No cache policies, no 256-bit ops
// (both measured regressions). At 10.8us we run ~86% of the absolute LTS
// crossbar cap (~6.9 TB/s); this targets the ramp phase via +8 warps/SM.

static constexpr int HOP = 64;
static constexpr long long NUM_FRAMES = 131072;
static constexpr long long N_VEC4 = NUM_FRAMES * HOP / 4;  // 2,097,152
static constexpr int DELAY_VEC4 = (3 * HOP) / 4;           // 48 float4s

static constexpr int NUM_SMS = 148;
static constexpr int BLOCKS  = NUM_SMS * 8;                // 1184
static constexpr int THREADS = 256;
static constexpr int STRIDE  = BLOCKS * THREADS;           // 303104, %16 == 0
static constexpr int ITERS   = 7;                          // 6 full + 1 partial

__global__ void __launch_bounds__(THREADS, 8)
stft_delay_scale_kernel(const float4* __restrict__ chunk4,
                        const float*  __restrict__ aw,
                        const float*  __restrict__ sw,
                        float4* __restrict__ out4)
{
    const int i0 = blockIdx.x * THREADS + threadIdx.x;

    // Column of this lane within the 64-wide row; invariant across the
    // strided loop because STRIDE % 16 == 0.
    const int j0   = (i0 & 15) << 2;
    const int base = j0 + (j0 < 32 ? 128 : 64);            // float4-aligned

    const float4 a = *reinterpret_cast<const float4*>(aw + base);
    const float4 s = *reinterpret_cast<const float4*>(sw + base);
    const float4 w = make_float4(a.x * s.x, a.y * s.y, a.z * s.z, a.w * s.w);

    // Front-batch all independent loads (MLP = 7; last iter guarded).
    float4 v[ITERS];
#pragma unroll
    for (int k = 0; k < ITERS; k++) {
        const long long i = (long long)i0 + (long long)k * STRIDE;
        const bool in_range = (k < ITERS - 1) || (i < N_VEC4);
        if (in_range && i >= DELAY_VEC4) {
            v[k] = __ldg(chunk4 + (i - DELAY_VEC4));
        } else {
            v[k] = make_float4(0.f, 0.f, 0.f, 0.f);
        }
    }

#pragma unroll
    for (int k = 0; k < ITERS; k++) {
        const long long i = (long long)i0 + (long long)k * STRIDE;
        if (k < ITERS - 1 || i < N_VEC4) {
            float4 o;
            o.x = v[k].x * w.x;
            o.y = v[k].y * w.y;
            o.z = v[k].z * w.z;
            o.w = v[k].w * w.w;
            out4[i] = o;
        }
    }
}

extern "C" void kernel_launch(void* const* d_in, const int* in_sizes, int n_in,
                              void* d_out, int out_size)
{
    const float4* chunk4 = reinterpret_cast<const float4*>(d_in[0]);
    const float*  aw     = reinterpret_cast<const float*>(d_in[1]);
    const float*  sw     = reinterpret_cast<const float*>(d_in[2]);
    float4*       out4   = reinterpret_cast<float4*>(d_out);

    stft_delay_scale_kernel<<<BLOCKS, THREADS>>>(chunk4, aw, sw, out4);
}

// round 9
// speedup vs baseline: 1.1852x; 1.0123x over previous
#include <cuda_runtime.h>
#include <cstdint>

// StreamingSTFT collapses analytically:
//   irfft(rfft(x)) == x  =>  frame = in_buf * aw * sw
//   sw nonzero only on [96,160)  =>  overlap-add reduces to
//   out[i][j] = chunk[i-3][j] * W[j]   (i >= 3), else 0
//   W[j] = aw[j+128]*sw[j+128] (j<32) ; aw[j+64]*sw[j+64] (j>=32)
//
// R8: R7 shape (148*8 = 1184 blocks, 64 warps/SM single balanced wave,
// plain __ldg float4, 7 front-batched loads, window hoisted) with all
// index math in 32-bit (max index 2^21-1 << 2^31) — halves the address
// ALU in front of each LDG and shortens the ramp-phase critical path.

static constexpr int HOP = 64;
static constexpr int NUM_FRAMES = 131072;
static constexpr int N_VEC4 = NUM_FRAMES * HOP / 4;        // 2,097,152
static constexpr int DELAY_VEC4 = (3 * HOP) / 4;           // 48 float4s

static constexpr int NUM_SMS = 148;
static constexpr int BLOCKS  = NUM_SMS * 8;                // 1184
static constexpr int THREADS = 256;
static constexpr int STRIDE  = BLOCKS * THREADS;           // 303104, %16 == 0
static constexpr int ITERS   = 7;                          // 6 full + 1 partial

__global__ void __launch_bounds__(THREADS, 8)
stft_delay_scale_kernel(const float4* __restrict__ chunk4,
                        const float*  __restrict__ aw,
                        const float*  __restrict__ sw,
                        float4* __restrict__ out4)
{
    const int i0 = blockIdx.x * THREADS + threadIdx.x;

    // Column of this lane within the 64-wide row; invariant across the
    // strided loop because STRIDE % 16 == 0.
    const int j0   = (i0 & 15) << 2;
    const int base = j0 + (j0 < 32 ? 128 : 64);            // float4-aligned

    const float4 a = *reinterpret_cast<const float4*>(aw + base);
    const float4 s = *reinterpret_cast<const float4*>(sw + base);
    const float4 w = make_float4(a.x * s.x, a.y * s.y, a.z * s.z, a.w * s.w);

    // Front-batch all independent loads (MLP = 7; only iter 6 is guarded).
    float4 v[ITERS];
#pragma unroll
    for (int k = 0; k < ITERS; k++) {
        const int i = i0 + k * STRIDE;                     // 32-bit, exact
        const bool in_range = (k < ITERS - 1) || (i < N_VEC4);
        if (in_range && i >= DELAY_VEC4) {
            v[k] = __ldg(chunk4 + (i - DELAY_VEC4));
        } else {
            v[k] = make_float4(0.f, 0.f, 0.f, 0.f);
        }
    }

#pragma unroll
    for (int k = 0; k < ITERS; k++) {
        const int i = i0 + k * STRIDE;
        if (k < ITERS - 1 || i < N_VEC4) {
            float4 o;
            o.x = v[k].x * w.x;
            o.y = v[k].y * w.y;
            o.z = v[k].z * w.z;
            o.w = v[k].w * w.w;
            out4[i] = o;
        }
    }
}

extern "C" void kernel_launch(void* const* d_in, const int* in_sizes, int n_in,
                              void* d_out, int out_size)
{
    const float4* chunk4 = reinterpret_cast<const float4*>(d_in[0]);
    const float*  aw     = reinterpret_cast<const float*>(d_in[1]);
    const float*  sw     = reinterpret_cast<const float*>(d_in[2]);
    float4*       out4   = reinterpret_cast<float4*>(d_out);

    stft_delay_scale_kernel<<<BLOCKS, THREADS>>>(chunk4, aw, sw, out4);
}